// round 5
// baseline (speedup 1.0000x reference)
#include <cuda_runtime.h>

// Capsule routing layer — s32-redux + magic-number fixed point (sm_100).
// 1 block (256 thr) per node; warp = capsule k, lane = neighbor m.
// z in 8 packed f32x2 regs; u replicated across lanes at 2^21 fixed-point scale
// (scale cancels in p = z.u_hat via invn; descaled only at the final store).
// F2I is done by folding MAGIC=1.5*2^23 into the FMA addend: the fixed-point
// integer appears directly in the float bit pattern (exact, ulp=1 in binade).

static __device__ __forceinline__ int redux_add_s32(int v) {
    int r;
    asm("redux.sync.add.s32 %0, %1, 0xffffffff;" : "=r"(r) : "r"(v));
    return r;
}
static __device__ __forceinline__ unsigned long long pack2(float lo, float hi) {
    unsigned long long r;
    asm("mov.b64 %0, {%1, %2};" : "=l"(r) : "f"(lo), "f"(hi));
    return r;
}
static __device__ __forceinline__ void unpack2(unsigned long long v, float& lo, float& hi) {
    asm("mov.b64 {%0, %1}, %2;" : "=f"(lo), "=f"(hi) : "l"(v));
}
static __device__ __forceinline__ unsigned long long fma2(
    unsigned long long a, unsigned long long b, unsigned long long c) {
    unsigned long long r;
    asm("fma.rn.f32x2 %0, %1, %2, %3;" : "=l"(r) : "l"(a), "l"(b), "l"(c));
    return r;
}

__global__ __launch_bounds__(256, 5)
void routing_kernel(const float* __restrict__ x,
                    const int*   __restrict__ nbrs,
                    const float* __restrict__ param_p,
                    const int*   __restrict__ miter_p,
                    float*       __restrict__ out,
                    int n)
{
    constexpr int DIM = 128, DD = 16, M = 32;
    constexpr float MAGIC = 12582912.0f;            // 1.5 * 2^23, bits 0x4B400000
    constexpr unsigned BIAS32 = 0x68000000u;        // (32 * 0x4B400000) mod 2^32
    constexpr float S21  = 2097152.0f;              // 2^21 phase-B fixed point
    constexpr float IS21 = 1.0f / 2097152.0f;
    constexpr float S20  = 1048576.0f;              // 2^20 exp-sum fixed point
    constexpr float IS20 = 1.0f / 1048576.0f;

    __shared__ __align__(16) float e_sh[2][M][36];  // padded rows, float4-readable
    __shared__ __align__(16) float ubm_sh[8][DD];   // ub*2^21/32 + MAGIC, per capsule

    const int node = blockIdx.x;
    const int tid  = threadIdx.x;
    const int k    = tid >> 5;     // warp = capsule
    const int lane = tid & 31;     // lane = neighbor m

    const float param = *param_p;
    int max_iter = *miter_p;
    if (max_iter < 1 || max_iter > 1000) {          // defensive scalar decode
        float f = __int_as_float(max_iter);
        max_iter = (f >= 1.0f && f <= 1000.0f) ? (int)f : 6;
    }

    // ---- own features: normalize, scale to 2^21/32, add MAGIC, park in shared ----
    {
        const float4* src = reinterpret_cast<const float4*>(x + (size_t)node * DIM + k * DD);
        float4 t0 = src[0], t1 = src[1], t2 = src[2], t3 = src[3];
        float v[DD] = {t0.x,t0.y,t0.z,t0.w, t1.x,t1.y,t1.z,t1.w,
                       t2.x,t2.y,t2.z,t2.w, t3.x,t3.y,t3.z,t3.w};
        float ss = 0.f;
        #pragma unroll
        for (int d = 0; d < DD; ++d) ss = fmaf(v[d], v[d], ss);
        const float sc = __fdividef(S21 / 32.0f, fmaxf(sqrtf(ss), 1e-12f));
        if (lane == 0) {
            float4* dst = reinterpret_cast<float4*>(&ubm_sh[k][0]);
            dst[0] = make_float4(fmaf(v[0],sc,MAGIC),  fmaf(v[1],sc,MAGIC),
                                 fmaf(v[2],sc,MAGIC),  fmaf(v[3],sc,MAGIC));
            dst[1] = make_float4(fmaf(v[4],sc,MAGIC),  fmaf(v[5],sc,MAGIC),
                                 fmaf(v[6],sc,MAGIC),  fmaf(v[7],sc,MAGIC));
            dst[2] = make_float4(fmaf(v[8],sc,MAGIC),  fmaf(v[9],sc,MAGIC),
                                 fmaf(v[10],sc,MAGIC), fmaf(v[11],sc,MAGIC));
            dst[3] = make_float4(fmaf(v[12],sc,MAGIC), fmaf(v[13],sc,MAGIC),
                                 fmaf(v[14],sc,MAGIC), fmaf(v[15],sc,MAGIC));
        }
        __syncwarp();
    }

    // ---- gather neighbor capsule row, L2-normalize, keep packed ----
    unsigned long long zp[8];
    {
        const int idx = nbrs[node * M + lane];
        float z[DD];
        if ((unsigned)idx < (unsigned)n) {
            const float4* src = reinterpret_cast<const float4*>(x + (size_t)idx * DIM + k * DD);
            float4 t0 = src[0], t1 = src[1], t2 = src[2], t3 = src[3];
            z[0]=t0.x; z[1]=t0.y; z[2]=t0.z; z[3]=t0.w;
            z[4]=t1.x; z[5]=t1.y; z[6]=t1.z; z[7]=t1.w;
            z[8]=t2.x; z[9]=t2.y; z[10]=t2.z; z[11]=t2.w;
            z[12]=t3.x; z[13]=t3.y; z[14]=t3.z; z[15]=t3.w;
            float ss = 0.f;
            #pragma unroll
            for (int d = 0; d < DD; ++d) ss = fmaf(z[d], z[d], ss);
            const float sc = __fdividef(1.0f, fmaxf(sqrtf(ss), 1e-12f));
            #pragma unroll
            for (int d = 0; d < DD; ++d) z[d] *= sc;
        } else {
            #pragma unroll
            for (int d = 0; d < DD; ++d) z[d] = 0.f;
        }
        #pragma unroll
        for (int j = 0; j < 8; ++j) zp[j] = pack2(z[2*j], z[2*j+1]);
    }

    unsigned long long up[8];    // u at 2^21 scale, replicated, packed
    float invn = 1.0f;           // 1/||u_fixed|| (folds normalize + descale into p)
    const float w0 = param * (1.0f / 32.0f) + (1.0f - param) * (1.0f / 8.0f);

    const unsigned long long* ubm2 =
        reinterpret_cast<const unsigned long long*>(&ubm_sh[k][0]);

    for (int it = 0; it < max_iter; ++it) {
        float w;
        if (it == 0) {
            w = w0;                                  // p = 0 -> uniform softmaxes
        } else {
            // p = <z, u_hat> : packed dot on replicated up
            unsigned long long pp = 0ull;
            #pragma unroll
            for (int j = 0; j < 8; ++j) pp = fma2(zp[j], up[j], pp);
            float plo, phi; unpack2(pp, plo, phi);
            const float p = (plo + phi) * invn;      // |p| <= 1
            const float e = __expf(p);

            // softmax-over-neighbors denom: magic-encoded exact integer redux
            const int ei = __float_as_int(fmaf(e, S20, MAGIC));
            const int smi = (int)((unsigned)redux_add_s32(ei) - BIAS32);
            const float sm = (float)smi * IS20;

            // softmax-over-capsules denom: cross-warp via shared
            e_sh[it & 1][lane][k] = e;
            __syncthreads();
            const float4* er = reinterpret_cast<const float4*>(&e_sh[it & 1][lane][0]);
            const float4 ea = er[0], eb = er[1];
            const float sk = ((ea.x + ea.y) + (ea.z + ea.w))
                           + ((eb.x + eb.y) + (eb.z + eb.w));

            w = e * (__fdividef(param, sm) + __fdividef(1.0f - param, sk));
        }

        // u[d] = 2^21*(sum_m w*z[m][d] + ub[d]/... ) via magic-biased redux.
        // |w*z + ub/32| <= ~1.03 at 2^21 scale < 2^22: binade-exact encode.
        const float ws = w * S21;
        const unsigned long long ws2 = pack2(ws, ws);
        unsigned long long ss2 = 0ull;
        #pragma unroll
        for (int j = 0; j < 8; ++j) {
            const unsigned long long t = fma2(ws2, zp[j], ubm2[j]); // LDS.64 bcast
            float f0, f1; unpack2(t, f0, f1);
            const int s0 = (int)((unsigned)redux_add_s32(__float_as_int(f0)) - BIAS32);
            const int s1 = (int)((unsigned)redux_add_s32(__float_as_int(f1)) - BIAS32);
            up[j] = pack2((float)s0, (float)s1);
            ss2 = fma2(up[j], up[j], ss2);
        }
        float slo, shi; unpack2(ss2, slo, shi);
        invn = __frsqrt_rn(fmaxf(slo + shi, 1e-20f));
    }

    // every lane holds the full result; lane 0 of each warp writes 64B
    if (lane == 0) {
        float uo[DD];
        #pragma unroll
        for (int j = 0; j < 8; ++j) {
            float a, b; unpack2(up[j], a, b);
            uo[2*j] = a * IS21; uo[2*j+1] = b * IS21;
        }
        float4* dst = reinterpret_cast<float4*>(out + (size_t)node * DIM + k * DD);
        dst[0] = make_float4(uo[0],  uo[1],  uo[2],  uo[3]);
        dst[1] = make_float4(uo[4],  uo[5],  uo[6],  uo[7]);
        dst[2] = make_float4(uo[8],  uo[9],  uo[10], uo[11]);
        dst[3] = make_float4(uo[12], uo[13], uo[14], uo[15]);
    }
}

extern "C" void kernel_launch(void* const* d_in, const int* in_sizes, int n_in,
                              void* d_out, int out_size)
{
    const float* x     = (const float*)d_in[0];
    const int*   nbrs  = (const int*)d_in[1];
    const float* param = (const float*)d_in[2];
    const int*   miter = (const int*)d_in[3];
    float*       out   = (float*)d_out;

    const int n = in_sizes[0] / 128;
    routing_kernel<<<n, 256>>>(x, nbrs, param, miter, out, n);
}

// round 6
// speedup vs baseline: 1.0227x; 1.0227x over previous
#include <cuda_runtime.h>

// Capsule routing layer — s32-redux + fused magic fixed-point encode (sm_100).
// 1 block (256 thr) per node; warp = capsule k, lane = neighbor m.
// z / magic-biased ub / u all packed f32x2 in registers.
// Encode: f = fma2(w*2^21, z, ub*2^21/32 + MAGIC) puts the fixed-point integer
// directly in the float bit pattern (MAGIC = 1.5*2^23, ulp = 1 in binade).
// redux sums bit patterns exactly; one IADD removes 32*MAGIC, one I2F restores.

static __device__ __forceinline__ int redux_add_s32(int v) {
    int r;
    asm("redux.sync.add.s32 %0, %1, 0xffffffff;" : "=r"(r) : "r"(v));
    return r;
}
static __device__ __forceinline__ unsigned long long pack2(float lo, float hi) {
    unsigned long long r;
    asm("mov.b64 %0, {%1, %2};" : "=l"(r) : "f"(lo), "f"(hi));
    return r;
}
static __device__ __forceinline__ void unpack2(unsigned long long v, float& lo, float& hi) {
    asm("mov.b64 {%0, %1}, %2;" : "=f"(lo), "=f"(hi) : "l"(v));
}
static __device__ __forceinline__ unsigned long long fma2(
    unsigned long long a, unsigned long long b, unsigned long long c) {
    unsigned long long r;
    asm("fma.rn.f32x2 %0, %1, %2, %3;" : "=l"(r) : "l"(a), "l"(b), "l"(c));
    return r;
}
static __device__ __forceinline__ float ex2f(float x) {
    float r;
    asm("ex2.approx.f32 %0, %1;" : "=f"(r) : "f"(x));
    return r;
}

__global__ __launch_bounds__(256, 4)
void routing_kernel(const float* __restrict__ x,
                    const int*   __restrict__ nbrs,
                    const float* __restrict__ param_p,
                    const int*   __restrict__ miter_p,
                    float*       __restrict__ out,
                    int n)
{
    constexpr int DIM = 128, DD = 16, M = 32;
    constexpr float MAGIC  = 12582912.0f;           // 1.5*2^23, bits 0x4B400000
    constexpr unsigned BIAS32 = 0x68000000u;        // (32*0x4B400000) mod 2^32
    constexpr float S21  = 2097152.0f;              // 2^21 phase-B fixed point
    constexpr float IS21 = 1.0f / 2097152.0f;
    constexpr float S20  = 1048576.0f;              // 2^20 exp-sum fixed point
    constexpr float LOG2E = 1.4426950408889634f;

    __shared__ __align__(16) float e_sh[2][M][36];  // padded rows, float4-readable

    const int node = blockIdx.x;
    const int tid  = threadIdx.x;
    const int k    = tid >> 5;     // warp = capsule
    const int lane = tid & 31;     // lane = neighbor m

    const float param = *param_p;
    int max_iter = *miter_p;
    if (max_iter < 1 || max_iter > 1000) {          // defensive scalar decode
        float f = __int_as_float(max_iter);
        max_iter = (f >= 1.0f && f <= 1000.0f) ? (int)f : 6;
    }

    // ---- own features: normalize, scale to 2^21/32, MAGIC-bias, keep packed ----
    unsigned long long ubm[8];
    {
        const float4* src = reinterpret_cast<const float4*>(x + (size_t)node * DIM + k * DD);
        float4 t0 = src[0], t1 = src[1], t2 = src[2], t3 = src[3];
        float v[DD] = {t0.x,t0.y,t0.z,t0.w, t1.x,t1.y,t1.z,t1.w,
                       t2.x,t2.y,t2.z,t2.w, t3.x,t3.y,t3.z,t3.w};
        float ss = 0.f;
        #pragma unroll
        for (int d = 0; d < DD; ++d) ss = fmaf(v[d], v[d], ss);
        const float sc = __fdividef(S21 / 32.0f, fmaxf(sqrtf(ss), 1e-12f));
        #pragma unroll
        for (int j = 0; j < 8; ++j)
            ubm[j] = pack2(fmaf(v[2*j], sc, MAGIC), fmaf(v[2*j+1], sc, MAGIC));
    }

    // ---- gather neighbor capsule row, L2-normalize, keep packed ----
    unsigned long long zp[8];
    {
        const int idx = nbrs[node * M + lane];
        float z[DD];
        if ((unsigned)idx < (unsigned)n) {
            const float4* src = reinterpret_cast<const float4*>(x + (size_t)idx * DIM + k * DD);
            float4 t0 = src[0], t1 = src[1], t2 = src[2], t3 = src[3];
            z[0]=t0.x; z[1]=t0.y; z[2]=t0.z; z[3]=t0.w;
            z[4]=t1.x; z[5]=t1.y; z[6]=t1.z; z[7]=t1.w;
            z[8]=t2.x; z[9]=t2.y; z[10]=t2.z; z[11]=t2.w;
            z[12]=t3.x; z[13]=t3.y; z[14]=t3.z; z[15]=t3.w;
            float ss = 0.f;
            #pragma unroll
            for (int d = 0; d < DD; ++d) ss = fmaf(z[d], z[d], ss);
            const float sc = __fdividef(1.0f, fmaxf(sqrtf(ss), 1e-12f));
            #pragma unroll
            for (int d = 0; d < DD; ++d) z[d] *= sc;
        } else {
            #pragma unroll
            for (int d = 0; d < DD; ++d) z[d] = 0.f;
        }
        #pragma unroll
        for (int j = 0; j < 8; ++j) zp[j] = pack2(z[2*j], z[2*j+1]);
    }

    unsigned long long up[8];    // u at 2^21 scale, replicated, packed
    float il = 0.f;              // invn * log2(e), folds normalize+descale into exp
    const float w0 = param * (1.0f / 32.0f) + (1.0f - param) * (1.0f / 8.0f);
    const float paramS20  = param * S20;
    const float q1        = 1.0f - param;

    // hoisted shared addresses
    float* e_w0 = &e_sh[0][lane][0];
    float* e_w1 = &e_sh[1][lane][0];

    for (int it = 0; it < max_iter; ++it) {
        float w;
        if (it == 0) {
            w = w0;                                  // p = 0 -> uniform softmaxes
        } else {
            // p = <z, u_hat> : packed dot on replicated up
            unsigned long long pp = 0ull;
            #pragma unroll
            for (int j = 0; j < 8; ++j) pp = fma2(zp[j], up[j], pp);
            float plo, phi; unpack2(pp, plo, phi);
            const float e = ex2f((plo + phi) * il);  // exp(p*invn), |p*invn|<=1

            // softmax-over-neighbors denom: magic-encoded exact integer redux
            const int ei = __float_as_int(fmaf(e, S20, MAGIC));
            const int smi = (int)((unsigned)redux_add_s32(ei) - BIAS32);
            // param/sm_real = param*S20/smi
            const float t1v = __fdividef(paramS20, (float)smi);

            // softmax-over-capsules denom: cross-warp via shared
            float* ew = (it & 1) ? e_w1 : e_w0;
            ew[k] = e;
            __syncthreads();
            const float4 ea = *reinterpret_cast<const float4*>(ew);
            const float4 eb = *reinterpret_cast<const float4*>(ew + 4);
            const float sk = ((ea.x + ea.y) + (ea.z + ea.w))
                           + ((eb.x + eb.y) + (eb.z + eb.w));

            w = e * (t1v + __fdividef(q1, sk));
        }

        // u[d] = 2^21*(sum_m w*z[m][d] + ub[d]) via magic-biased redux.
        const float ws = w * S21;
        const unsigned long long ws2 = pack2(ws, ws);
        if (it + 1 < max_iter) {
            unsigned long long ss2 = 0ull;
            #pragma unroll
            for (int j = 0; j < 8; ++j) {
                const unsigned long long t = fma2(ws2, zp[j], ubm[j]);
                float f0, f1; unpack2(t, f0, f1);
                const int s0 = (int)((unsigned)redux_add_s32(__float_as_int(f0)) - BIAS32);
                const int s1 = (int)((unsigned)redux_add_s32(__float_as_int(f1)) - BIAS32);
                up[j] = pack2((float)s0, (float)s1);
                ss2 = fma2(up[j], up[j], ss2);
            }
            float slo, shi; unpack2(ss2, slo, shi);
            il = __frsqrt_rn(fmaxf(slo + shi, 1e-20f)) * LOG2E;
        } else {
            #pragma unroll
            for (int j = 0; j < 8; ++j) {
                const unsigned long long t = fma2(ws2, zp[j], ubm[j]);
                float f0, f1; unpack2(t, f0, f1);
                const int s0 = (int)((unsigned)redux_add_s32(__float_as_int(f0)) - BIAS32);
                const int s1 = (int)((unsigned)redux_add_s32(__float_as_int(f1)) - BIAS32);
                up[j] = pack2((float)s0, (float)s1);
            }
        }
    }

    // every lane holds the full result; lane 0 of each warp writes 64B
    if (lane == 0) {
        float uo[DD];
        #pragma unroll
        for (int j = 0; j < 8; ++j) {
            float a, b; unpack2(up[j], a, b);
            uo[2*j] = a * IS21; uo[2*j+1] = b * IS21;
        }
        float4* dst = reinterpret_cast<float4*>(out + (size_t)node * DIM + k * DD);
        dst[0] = make_float4(uo[0],  uo[1],  uo[2],  uo[3]);
        dst[1] = make_float4(uo[4],  uo[5],  uo[6],  uo[7]);
        dst[2] = make_float4(uo[8],  uo[9],  uo[10], uo[11]);
        dst[3] = make_float4(uo[12], uo[13], uo[14], uo[15]);
    }
}

extern "C" void kernel_launch(void* const* d_in, const int* in_sizes, int n_in,
                              void* d_out, int out_size)
{
    const float* x     = (const float*)d_in[0];
    const int*   nbrs  = (const int*)d_in[1];
    const float* param = (const float*)d_in[2];
    const int*   miter = (const int*)d_in[3];
    float*       out   = (float*)d_out;

    const int n = in_sizes[0] / 128;
    routing_kernel<<<n, 256>>>(x, nbrs, param, miter, out, n);
}

// round 7
// speedup vs baseline: 1.0708x; 1.0470x over previous
#include <cuda_runtime.h>

// Capsule routing layer — s32-redux fixed point, fully unrolled (sm_100).
// 1 block (256 thr) per node; warp = capsule k, lane = neighbor m.
// z / ub / u all packed f32x2 in registers; u replicated across lanes at 2^21
// fixed-point scale (scale cancels in p = z.u_hat via il; descaled at store).

static __device__ __forceinline__ int redux_add_s32(int v) {
    int r;
    asm("redux.sync.add.s32 %0, %1, 0xffffffff;" : "=r"(r) : "r"(v));
    return r;
}
static __device__ __forceinline__ unsigned long long pack2(float lo, float hi) {
    unsigned long long r;
    asm("mov.b64 %0, {%1, %2};" : "=l"(r) : "f"(lo), "f"(hi));
    return r;
}
static __device__ __forceinline__ void unpack2(unsigned long long v, float& lo, float& hi) {
    asm("mov.b64 {%0, %1}, %2;" : "=f"(lo), "=f"(hi) : "l"(v));
}
static __device__ __forceinline__ unsigned long long fma2(
    unsigned long long a, unsigned long long b, unsigned long long c) {
    unsigned long long r;
    asm("fma.rn.f32x2 %0, %1, %2, %3;" : "=l"(r) : "l"(a), "l"(b), "l"(c));
    return r;
}
static __device__ __forceinline__ float ex2f(float x) {
    float r;
    asm("ex2.approx.f32 %0, %1;" : "=f"(r) : "f"(x));
    return r;
}

constexpr float S21   = 2097152.0f;              // 2^21 phase-B fixed point
constexpr float IS21  = 1.0f / 2097152.0f;
constexpr float S20   = 1048576.0f;              // 2^20 exp-sum fixed point
constexpr float LOG2E = 1.4426950408889634f;

// Core routing loop. UNROLL_N > 0: compile-time trip count (fully unrolled);
// UNROLL_N == 0: runtime max_iter loop.
template <int UNROLL_N>
static __device__ __forceinline__ void routing_core(
    const unsigned long long zp[8], const unsigned long long ubs[8],
    unsigned long long up[8],
    float (*e_sh)[36] /* [2*32][36] flattened rows */,
    int lane, int k, float param, float q1, float w0, int max_iter)
{
    const float paramS20 = param * S20;
    float il = 0.f;
    float* e_w0 = &e_sh[lane][0];
    float* e_w1 = &e_sh[32 + lane][0];

    const int trip = UNROLL_N > 0 ? UNROLL_N : max_iter;
    #pragma unroll
    for (int it = 0; it < trip; ++it) {
        float w;
        if (it == 0) {
            w = w0;                                  // p = 0 -> uniform softmaxes
        } else {
            // p = <z, u_hat> : packed dot on replicated up
            unsigned long long pp = 0ull;
            #pragma unroll
            for (int j = 0; j < 8; ++j) pp = fma2(zp[j], up[j], pp);
            float plo, phi; unpack2(pp, plo, phi);
            const float e = ex2f((plo + phi) * il);  // exp(p/||u||), |.|<=1

            // softmax-over-neighbors denom: exact integer redux (cvt-pipe F2I)
            const int ei = __float2int_rn(e * S20);
            const float smf = (float)redux_add_s32(ei);   // = S20 * sum_m e

            // softmax-over-capsules denom: cross-warp via shared
            float* ew = (it & 1) ? e_w1 : e_w0;
            ew[k] = e;
            __syncthreads();
            const float4 ea = *reinterpret_cast<const float4*>(ew);
            const float4 eb = *reinterpret_cast<const float4*>(ew + 4);
            const float sk = ((ea.x + ea.y) + (ea.z + ea.w))
                           + ((eb.x + eb.y) + (eb.z + eb.w));

            // w = e*(param/sm + q1/sk) with a single divide:
            const float num = fmaf(q1, smf, paramS20 * sk);
            w = e * __fdividef(num, smf * sk);
        }

        // u[d] = 2^21*(sum_m w*z[m][d] + ub[d]) via exact integer redux
        const float ws = w * S21;
        const unsigned long long ws2 = pack2(ws, ws);
        const bool last = (it + 1 >= trip);
        unsigned long long ss2 = 0ull;
        #pragma unroll
        for (int j = 0; j < 8; ++j) {
            const unsigned long long t = fma2(ws2, zp[j], ubs[j]);
            float f0, f1; unpack2(t, f0, f1);
            const float u0 = (float)redux_add_s32(__float2int_rn(f0));
            const float u1 = (float)redux_add_s32(__float2int_rn(f1));
            up[j] = pack2(u0, u1);
            if (!last) ss2 = fma2(up[j], up[j], ss2);
        }
        if (!last) {
            float slo, shi; unpack2(ss2, slo, shi);
            il = __frsqrt_rn(fmaxf(slo + shi, 1e-20f)) * LOG2E;
        }
    }
}

__global__ __launch_bounds__(256, 4)
void routing_kernel(const float* __restrict__ x,
                    const int*   __restrict__ nbrs,
                    const float* __restrict__ param_p,
                    const int*   __restrict__ miter_p,
                    float*       __restrict__ out,
                    int n)
{
    constexpr int DIM = 128, DD = 16, M = 32;

    __shared__ __align__(16) float e_sh[2 * M][36];  // padded rows, float4-readable

    const int node = blockIdx.x;
    const int tid  = threadIdx.x;
    const int k    = tid >> 5;     // warp = capsule
    const int lane = tid & 31;     // lane = neighbor m

    const float param = *param_p;
    int max_iter = *miter_p;
    if (max_iter < 1 || max_iter > 1000) {           // defensive scalar decode
        float f = __int_as_float(max_iter);
        max_iter = (f >= 1.0f && f <= 1000.0f) ? (int)f : 6;
    }

    // ---- own features: normalize, scale to 2^21/32, keep packed ----
    unsigned long long ubs[8];
    {
        const float4* src = reinterpret_cast<const float4*>(x + (size_t)node * DIM + k * DD);
        float4 t0 = src[0], t1 = src[1], t2 = src[2], t3 = src[3];
        float v[DD] = {t0.x,t0.y,t0.z,t0.w, t1.x,t1.y,t1.z,t1.w,
                       t2.x,t2.y,t2.z,t2.w, t3.x,t3.y,t3.z,t3.w};
        float ss = 0.f;
        #pragma unroll
        for (int d = 0; d < DD; ++d) ss = fmaf(v[d], v[d], ss);
        const float sc = __fdividef(S21 / 32.0f, fmaxf(sqrtf(ss), 1e-12f));
        #pragma unroll
        for (int j = 0; j < 8; ++j) ubs[j] = pack2(v[2*j] * sc, v[2*j+1] * sc);
    }

    // ---- gather neighbor capsule row, L2-normalize, keep packed ----
    unsigned long long zp[8];
    {
        const int idx = nbrs[node * M + lane];
        float z[DD];
        if ((unsigned)idx < (unsigned)n) {
            const float4* src = reinterpret_cast<const float4*>(x + (size_t)idx * DIM + k * DD);
            float4 t0 = src[0], t1 = src[1], t2 = src[2], t3 = src[3];
            z[0]=t0.x; z[1]=t0.y; z[2]=t0.z; z[3]=t0.w;
            z[4]=t1.x; z[5]=t1.y; z[6]=t1.z; z[7]=t1.w;
            z[8]=t2.x; z[9]=t2.y; z[10]=t2.z; z[11]=t2.w;
            z[12]=t3.x; z[13]=t3.y; z[14]=t3.z; z[15]=t3.w;
            float ss = 0.f;
            #pragma unroll
            for (int d = 0; d < DD; ++d) ss = fmaf(z[d], z[d], ss);
            const float sc = __fdividef(1.0f, fmaxf(sqrtf(ss), 1e-12f));
            #pragma unroll
            for (int d = 0; d < DD; ++d) z[d] *= sc;
        } else {
            #pragma unroll
            for (int d = 0; d < DD; ++d) z[d] = 0.f;
        }
        #pragma unroll
        for (int j = 0; j < 8; ++j) zp[j] = pack2(z[2*j], z[2*j+1]);
    }

    unsigned long long up[8];    // u at 2^21 scale, replicated, packed
    const float q1 = 1.0f - param;
    const float w0 = param * (1.0f / 32.0f) + q1 * (1.0f / 8.0f);

    if (max_iter == 6) {
        routing_core<6>(zp, ubs, up, e_sh, lane, k, param, q1, w0, 6);
    } else {
        routing_core<0>(zp, ubs, up, e_sh, lane, k, param, q1, w0, max_iter);
    }

    // every lane holds the full result; lane 0 of each warp writes 64B
    if (lane == 0) {
        float uo[DD];
        #pragma unroll
        for (int j = 0; j < 8; ++j) {
            float a, b; unpack2(up[j], a, b);
            uo[2*j] = a * IS21; uo[2*j+1] = b * IS21;
        }
        float4* dst = reinterpret_cast<float4*>(out + (size_t)node * DIM + k * DD);
        dst[0] = make_float4(uo[0],  uo[1],  uo[2],  uo[3]);
        dst[1] = make_float4(uo[4],  uo[5],  uo[6],  uo[7]);
        dst[2] = make_float4(uo[8],  uo[9],  uo[10], uo[11]);
        dst[3] = make_float4(uo[12], uo[13], uo[14], uo[15]);
    }
}

extern "C" void kernel_launch(void* const* d_in, const int* in_sizes, int n_in,
                              void* d_out, int out_size)
{
    const float* x     = (const float*)d_in[0];
    const int*   nbrs  = (const int*)d_in[1];
    const float* param = (const float*)d_in[2];
    const int*   miter = (const int*)d_in[3];
    float*       out   = (float*)d_out;

    const int n = in_sizes[0] / 128;
    routing_kernel<<<n, 256>>>(x, nbrs, param, miter, out, n);
}

// round 8
// speedup vs baseline: 1.1067x; 1.0335x over previous
#include <cuda_runtime.h>

// Capsule routing layer — s32-redux fixed point, fully unrolled, barrier-shadow
// scheduled (sm_100). 1 block (256 thr) per node; warp = capsule k, lane = m.
// z / ub / u packed f32x2 in registers; u replicated across lanes at 2^21
// fixed-point scale (scale cancels in p = z.u_hat via il; descaled at store).
// w is split w1 (needs only intra-warp redux) + w2 (needs cross-warp sk) so the
// w1 half of phase B executes in the __syncthreads shadow.

static __device__ __forceinline__ int redux_add_s32(int v) {
    int r;
    asm("redux.sync.add.s32 %0, %1, 0xffffffff;" : "=r"(r) : "r"(v));
    return r;
}
static __device__ __forceinline__ unsigned long long pack2(float lo, float hi) {
    unsigned long long r;
    asm("mov.b64 %0, {%1, %2};" : "=l"(r) : "f"(lo), "f"(hi));
    return r;
}
static __device__ __forceinline__ void unpack2(unsigned long long v, float& lo, float& hi) {
    asm("mov.b64 {%0, %1}, %2;" : "=f"(lo), "=f"(hi) : "l"(v));
}
static __device__ __forceinline__ unsigned long long fma2(
    unsigned long long a, unsigned long long b, unsigned long long c) {
    unsigned long long r;
    asm("fma.rn.f32x2 %0, %1, %2, %3;" : "=l"(r) : "l"(a), "l"(b), "l"(c));
    return r;
}
static __device__ __forceinline__ unsigned long long add2(
    unsigned long long a, unsigned long long b) {
    unsigned long long r;
    asm("add.rn.f32x2 %0, %1, %2;" : "=l"(r) : "l"(a), "l"(b));
    return r;
}
static __device__ __forceinline__ float ex2f(float x) {
    float r; asm("ex2.approx.f32 %0, %1;" : "=f"(r) : "f"(x)); return r;
}
static __device__ __forceinline__ float rsqf(float x) {
    float r; asm("rsqrt.approx.f32 %0, %1;" : "=f"(r) : "f"(x)); return r;
}
static __device__ __forceinline__ float rcpf(float x) {
    float r; asm("rcp.approx.f32 %0, %1;" : "=f"(r) : "f"(x)); return r;
}

constexpr float S21   = 2097152.0f;              // 2^21 phase-B fixed point
constexpr float IS21  = 1.0f / 2097152.0f;
constexpr float S20   = 1048576.0f;              // 2^20 exp-sum fixed point
constexpr float LOG2E = 1.4426950408889634f;

template <int UNROLL_N>
static __device__ __forceinline__ void routing_core(
    const unsigned long long zp[8], const unsigned long long ubs[8],
    unsigned long long up[8],
    float (*e_sh)[36], int lane, int k, float param, float q1, float w0,
    int max_iter)
{
    const float C1 = param * (S20 * S21);   // w1s = C1 * e / smf
    const float C2 = q1 * S21;              // w2s = C2 * e / sk
    float il = 0.f;                          // rsqrt(||u_fix||^2) * log2(e)
    float* e_w0 = &e_sh[lane][0];
    float* e_w1 = &e_sh[32 + lane][0];

    const int trip = UNROLL_N > 0 ? UNROLL_N : max_iter;
    #pragma unroll
    for (int it = 0; it < trip; ++it) {
        unsigned long long t[8];
        bool need_bar = false;
        float e = 0.f;
        float* ew = nullptr;

        if (it == 0) {
            const float ws = w0 * S21;
            const unsigned long long ws2 = pack2(ws, ws);
            #pragma unroll
            for (int j = 0; j < 8; ++j) t[j] = fma2(ws2, zp[j], ubs[j]);
        } else {
            // ---- pre-barrier: dot, exp, STS, neighbor-softmax half of w ----
            unsigned long long pp = 0ull;
            #pragma unroll
            for (int j = 0; j < 8; ++j) pp = fma2(zp[j], up[j], pp);
            float plo, phi; unpack2(pp, plo, phi);
            e = ex2f((plo + phi) * il);              // exp(p/||u||), |.|<=1

            ew = (it & 1) ? e_w1 : e_w0;
            ew[k] = e;                               // STS (pre-barrier)

            const int ei = __float2int_rn(e * S20);
            const float smf = (float)redux_add_s32(ei);   // S20 * sum_m e (exact)
            const float w1s = C1 * e * rcpf(smf);
            const unsigned long long w1s2 = pack2(w1s, w1s);
            #pragma unroll
            for (int j = 0; j < 8; ++j) t[j] = fma2(w1s2, zp[j], ubs[j]);
            need_bar = true;
        }

        if (need_bar) {
            __syncthreads();
            // ---- capsule-softmax half of w ----
            const float4 ea = *reinterpret_cast<const float4*>(ew);
            const float4 eb = *reinterpret_cast<const float4*>(ew + 4);
            const unsigned long long s =
                add2(add2(pack2(ea.x, ea.y), pack2(ea.z, ea.w)),
                     add2(pack2(eb.x, eb.y), pack2(eb.z, eb.w)));
            float s0, s1; unpack2(s, s0, s1);
            const float w2s = C2 * e * rcpf(s0 + s1);
            const unsigned long long w2s2 = pack2(w2s, w2s);
            #pragma unroll
            for (int j = 0; j < 8; ++j) t[j] = fma2(w2s2, zp[j], t[j]);
        }

        // ---- exact integer redux over neighbors; u replicated to all lanes ----
        const bool last = (it + 1 >= trip);
        unsigned long long ss2 = 0ull;
        #pragma unroll
        for (int j = 0; j < 8; ++j) {
            float f0, f1; unpack2(t[j], f0, f1);
            const float u0 = (float)redux_add_s32(__float2int_rn(f0));
            const float u1 = (float)redux_add_s32(__float2int_rn(f1));
            up[j] = pack2(u0, u1);
            if (!last) ss2 = fma2(up[j], up[j], ss2);
        }
        if (!last) {
            float slo, shi; unpack2(ss2, slo, shi);
            il = rsqf(fmaxf(slo + shi, 1e-20f)) * LOG2E;
        }
    }
}

__global__ __launch_bounds__(256, 4)
void routing_kernel(const float* __restrict__ x,
                    const int*   __restrict__ nbrs,
                    const float* __restrict__ param_p,
                    const int*   __restrict__ miter_p,
                    float*       __restrict__ out,
                    int n)
{
    constexpr int DIM = 128, DD = 16, M = 32;

    __shared__ __align__(16) float e_sh[2 * M][36];  // padded rows, float4-readable

    const int node = blockIdx.x;
    const int tid  = threadIdx.x;
    const int k    = tid >> 5;     // warp = capsule
    const int lane = tid & 31;     // lane = neighbor m

    const float param = *param_p;
    int max_iter = *miter_p;
    if (max_iter < 1 || max_iter > 1000) {           // defensive scalar decode
        float f = __int_as_float(max_iter);
        max_iter = (f >= 1.0f && f <= 1000.0f) ? (int)f : 6;
    }

    // ---- own features: normalize, scale to 2^21/32, keep packed ----
    unsigned long long ubs[8];
    {
        const float4* src = reinterpret_cast<const float4*>(x + (size_t)node * DIM + k * DD);
        float4 t0 = src[0], t1 = src[1], t2 = src[2], t3 = src[3];
        float v[DD] = {t0.x,t0.y,t0.z,t0.w, t1.x,t1.y,t1.z,t1.w,
                       t2.x,t2.y,t2.z,t2.w, t3.x,t3.y,t3.z,t3.w};
        float ss = 0.f;
        #pragma unroll
        for (int d = 0; d < DD; ++d) ss = fmaf(v[d], v[d], ss);
        const float sc = (S21 / 32.0f) * rsqf(fmaxf(ss, 1e-24f));
        #pragma unroll
        for (int j = 0; j < 8; ++j) ubs[j] = pack2(v[2*j] * sc, v[2*j+1] * sc);
    }

    // ---- gather neighbor capsule row, L2-normalize, keep packed ----
    unsigned long long zp[8];
    {
        const int idx = nbrs[node * M + lane];
        float z[DD];
        if ((unsigned)idx < (unsigned)n) {
            const float4* src = reinterpret_cast<const float4*>(x + (size_t)idx * DIM + k * DD);
            float4 t0 = src[0], t1 = src[1], t2 = src[2], t3 = src[3];
            z[0]=t0.x; z[1]=t0.y; z[2]=t0.z; z[3]=t0.w;
            z[4]=t1.x; z[5]=t1.y; z[6]=t1.z; z[7]=t1.w;
            z[8]=t2.x; z[9]=t2.y; z[10]=t2.z; z[11]=t2.w;
            z[12]=t3.x; z[13]=t3.y; z[14]=t3.z; z[15]=t3.w;
            float ss = 0.f;
            #pragma unroll
            for (int d = 0; d < DD; ++d) ss = fmaf(z[d], z[d], ss);
            const float sc = rsqf(fmaxf(ss, 1e-24f));
            #pragma unroll
            for (int d = 0; d < DD; ++d) z[d] *= sc;
        } else {
            #pragma unroll
            for (int d = 0; d < DD; ++d) z[d] = 0.f;
        }
        #pragma unroll
        for (int j = 0; j < 8; ++j) zp[j] = pack2(z[2*j], z[2*j+1]);
    }

    unsigned long long up[8];    // u at 2^21 scale, replicated, packed
    const float q1 = 1.0f - param;
    const float w0 = param * (1.0f / 32.0f) + q1 * (1.0f / 8.0f);

    if (max_iter == 6) {
        routing_core<6>(zp, ubs, up, e_sh, lane, k, param, q1, w0, 6);
    } else {
        routing_core<0>(zp, ubs, up, e_sh, lane, k, param, q1, w0, max_iter);
    }

    // every lane holds the full result; lane 0 of each warp writes 64B
    if (lane == 0) {
        float uo[DD];
        #pragma unroll
        for (int j = 0; j < 8; ++j) {
            float a, b; unpack2(up[j], a, b);
            uo[2*j] = a * IS21; uo[2*j+1] = b * IS21;
        }
        float4* dst = reinterpret_cast<float4*>(out + (size_t)node * DIM + k * DD);
        dst[0] = make_float4(uo[0],  uo[1],  uo[2],  uo[3]);
        dst[1] = make_float4(uo[4],  uo[5],  uo[6],  uo[7]);
        dst[2] = make_float4(uo[8],  uo[9],  uo[10], uo[11]);
        dst[3] = make_float4(uo[12], uo[13], uo[14], uo[15]);
    }
}

extern "C" void kernel_launch(void* const* d_in, const int* in_sizes, int n_in,
                              void* d_out, int out_size)
{
    const float* x     = (const float*)d_in[0];
    const int*   nbrs  = (const int*)d_in[1];
    const float* param = (const float*)d_in[2];
    const int*   miter = (const int*)d_in[3];
    float*       out   = (float*)d_out;

    const int n = in_sizes[0] / 128;
    routing_kernel<<<n, 256>>>(x, nbrs, param, miter, out, n);
}

// round 9
// speedup vs baseline: 1.1873x; 1.0729x over previous
#include <cuda_runtime.h>

// Capsule routing layer — s32-redux fixed point, fully unrolled (sm_100).
// 1 block (256 thr) per node; warp = capsule k, lane = neighbor m.
// z / ub / u packed f32x2 in registers; u replicated across lanes at 2^21
// fixed-point scale (cancels in p = z.u_hat via il; descaled at store).
// Long-latency scalar work (F2I/REDUX/rcp for the neighbor softmax) is placed
// BEFORE __syncthreads so it executes in the barrier-skew shadow; phase B runs
// once with the merged weight w = a1 + a2/sk.

static __device__ __forceinline__ int redux_add_s32(int v) {
    int r;
    asm("redux.sync.add.s32 %0, %1, 0xffffffff;" : "=r"(r) : "r"(v));
    return r;
}
static __device__ __forceinline__ unsigned long long pack2(float lo, float hi) {
    unsigned long long r;
    asm("mov.b64 %0, {%1, %2};" : "=l"(r) : "f"(lo), "f"(hi));
    return r;
}
static __device__ __forceinline__ void unpack2(unsigned long long v, float& lo, float& hi) {
    asm("mov.b64 {%0, %1}, %2;" : "=f"(lo), "=f"(hi) : "l"(v));
}
static __device__ __forceinline__ unsigned long long fma2(
    unsigned long long a, unsigned long long b, unsigned long long c) {
    unsigned long long r;
    asm("fma.rn.f32x2 %0, %1, %2, %3;" : "=l"(r) : "l"(a), "l"(b), "l"(c));
    return r;
}
static __device__ __forceinline__ unsigned long long add2(
    unsigned long long a, unsigned long long b) {
    unsigned long long r;
    asm("add.rn.f32x2 %0, %1, %2;" : "=l"(r) : "l"(a), "l"(b));
    return r;
}
static __device__ __forceinline__ float ex2f(float x) {
    float r; asm("ex2.approx.f32 %0, %1;" : "=f"(r) : "f"(x)); return r;
}
static __device__ __forceinline__ float rsqf(float x) {
    float r; asm("rsqrt.approx.f32 %0, %1;" : "=f"(r) : "f"(x)); return r;
}
static __device__ __forceinline__ float rcpf(float x) {
    float r; asm("rcp.approx.f32 %0, %1;" : "=f"(r) : "f"(x)); return r;
}

constexpr float S21   = 2097152.0f;              // 2^21 phase-B fixed point
constexpr float IS21  = 1.0f / 2097152.0f;
constexpr float S20   = 1048576.0f;              // 2^20 exp-sum fixed point
constexpr float LOG2E = 1.4426950408889634f;

template <int UNROLL_N>
static __device__ __forceinline__ void routing_core(
    const unsigned long long zp[8], const unsigned long long ubs[8],
    unsigned long long up[8],
    float (*e_sh)[36], int lane, int k, float param, float q1, float w0,
    int max_iter)
{
    const float C1 = param * (S20 * S21);   // a1 = C1 * e / smf
    const float C2 = q1 * S21;              // w  = a1 + C2 * e / sk
    float il = 0.f;                          // rsqrt(||u_fix||^2) * log2(e)
    float* e_w0 = &e_sh[lane][0];
    float* e_w1 = &e_sh[32 + lane][0];

    const int trip = UNROLL_N > 0 ? UNROLL_N : max_iter;
    #pragma unroll
    for (int it = 0; it < trip; ++it) {
        float w;
        if (it == 0) {
            w = w0 * S21;                            // p = 0 -> uniform softmaxes
        } else {
            // ---- pre-barrier (barrier-skew shadow): dot, exp, STS, sm-half ----
            unsigned long long pp = 0ull;
            #pragma unroll
            for (int j = 0; j < 8; ++j) pp = fma2(zp[j], up[j], pp);
            float plo, phi; unpack2(pp, plo, phi);
            const float e = ex2f((plo + phi) * il);  // exp(p/||u||), |.|<=1

            float* ew = (it & 1) ? e_w1 : e_w0;
            ew[k] = e;                               // STS (pre-barrier)

            const int ei = __float2int_rn(e * S20);
            const float smf = (float)redux_add_s32(ei);   // S20*sum_m e (exact)
            const float a1 = (C1 * e) * rcpf(smf);
            const float a2 = C2 * e;

            __syncthreads();
            // ---- post-barrier: capsule-softmax half, merged weight ----
            const float4 ea = *reinterpret_cast<const float4*>(ew);
            const float4 eb = *reinterpret_cast<const float4*>(ew + 4);
            const unsigned long long s =
                add2(add2(pack2(ea.x, ea.y), pack2(ea.z, ea.w)),
                     add2(pack2(eb.x, eb.y), pack2(eb.z, eb.w)));
            float s0, s1; unpack2(s, s0, s1);
            w = fmaf(a2, rcpf(s0 + s1), a1);         // already at 2^21 scale
        }

        // ---- phase B: t = w*z + ub; exact integer redux over neighbors ----
        const unsigned long long ws2 = pack2(w, w);
        const bool last = (it + 1 >= trip);
        unsigned long long ss2 = 0ull;
        #pragma unroll
        for (int j = 0; j < 8; ++j) {
            const unsigned long long t = fma2(ws2, zp[j], ubs[j]);
            float f0, f1; unpack2(t, f0, f1);
            const float u0 = (float)redux_add_s32(__float2int_rn(f0));
            const float u1 = (float)redux_add_s32(__float2int_rn(f1));
            up[j] = pack2(u0, u1);
            if (!last) ss2 = fma2(up[j], up[j], ss2);
        }
        if (!last) {
            float slo, shi; unpack2(ss2, slo, shi);
            il = rsqf(fmaxf(slo + shi, 1e-20f)) * LOG2E;
        }
    }
}

__global__ __launch_bounds__(256, 4)
void routing_kernel(const float* __restrict__ x,
                    const int*   __restrict__ nbrs,
                    const float* __restrict__ param_p,
                    const int*   __restrict__ miter_p,
                    float*       __restrict__ out,
                    int n)
{
    constexpr int DIM = 128, DD = 16, M = 32;

    __shared__ __align__(16) float e_sh[2 * M][36];  // padded rows, float4-readable

    const int node = blockIdx.x;
    const int tid  = threadIdx.x;
    const int k    = tid >> 5;     // warp = capsule
    const int lane = tid & 31;     // lane = neighbor m

    const float param = *param_p;
    int max_iter = *miter_p;
    if (max_iter < 1 || max_iter > 1000) {           // defensive scalar decode
        float f = __int_as_float(max_iter);
        max_iter = (f >= 1.0f && f <= 1000.0f) ? (int)f : 6;
    }

    // ---- own features: normalize, scale to 2^21/32, keep packed ----
    unsigned long long ubs[8];
    {
        const float4* src = reinterpret_cast<const float4*>(x + (size_t)node * DIM + k * DD);
        float4 t0 = src[0], t1 = src[1], t2 = src[2], t3 = src[3];
        float v[DD] = {t0.x,t0.y,t0.z,t0.w, t1.x,t1.y,t1.z,t1.w,
                       t2.x,t2.y,t2.z,t2.w, t3.x,t3.y,t3.z,t3.w};
        float ss = 0.f;
        #pragma unroll
        for (int d = 0; d < DD; ++d) ss = fmaf(v[d], v[d], ss);
        const float sc = (S21 / 32.0f) * rsqf(fmaxf(ss, 1e-24f));
        #pragma unroll
        for (int j = 0; j < 8; ++j) ubs[j] = pack2(v[2*j] * sc, v[2*j+1] * sc);
    }

    // ---- gather neighbor capsule row, L2-normalize, keep packed ----
    unsigned long long zp[8];
    {
        const int idx = nbrs[node * M + lane];
        float z[DD];
        if ((unsigned)idx < (unsigned)n) {
            const float4* src = reinterpret_cast<const float4*>(x + (size_t)idx * DIM + k * DD);
            float4 t0 = src[0], t1 = src[1], t2 = src[2], t3 = src[3];
            z[0]=t0.x; z[1]=t0.y; z[2]=t0.z; z[3]=t0.w;
            z[4]=t1.x; z[5]=t1.y; z[6]=t1.z; z[7]=t1.w;
            z[8]=t2.x; z[9]=t2.y; z[10]=t2.z; z[11]=t2.w;
            z[12]=t3.x; z[13]=t3.y; z[14]=t3.z; z[15]=t3.w;
            float ss = 0.f;
            #pragma unroll
            for (int d = 0; d < DD; ++d) ss = fmaf(z[d], z[d], ss);
            const float sc = rsqf(fmaxf(ss, 1e-24f));
            #pragma unroll
            for (int d = 0; d < DD; ++d) z[d] *= sc;
        } else {
            #pragma unroll
            for (int d = 0; d < DD; ++d) z[d] = 0.f;
        }
        #pragma unroll
        for (int j = 0; j < 8; ++j) zp[j] = pack2(z[2*j], z[2*j+1]);
    }

    unsigned long long up[8];    // u at 2^21 scale, replicated, packed
    const float q1 = 1.0f - param;
    const float w0 = param * (1.0f / 32.0f) + q1 * (1.0f / 8.0f);

    if (max_iter == 6) {
        routing_core<6>(zp, ubs, up, e_sh, lane, k, param, q1, w0, 6);
    } else {
        routing_core<0>(zp, ubs, up, e_sh, lane, k, param, q1, w0, max_iter);
    }

    // every lane holds the full result; lane 0 of each warp writes 64B
    if (lane == 0) {
        float uo[DD];
        #pragma unroll
        for (int j = 0; j < 8; ++j) {
            float a, b; unpack2(up[j], a, b);
            uo[2*j] = a * IS21; uo[2*j+1] = b * IS21;
        }
        float4* dst = reinterpret_cast<float4*>(out + (size_t)node * DIM + k * DD);
        dst[0] = make_float4(uo[0],  uo[1],  uo[2],  uo[3]);
        dst[1] = make_float4(uo[4],  uo[5],  uo[6],  uo[7]);
        dst[2] = make_float4(uo[8],  uo[9],  uo[10], uo[11]);
        dst[3] = make_float4(uo[12], uo[13], uo[14], uo[15]);
    }
}

extern "C" void kernel_launch(void* const* d_in, const int* in_sizes, int n_in,
                              void* d_out, int out_size)
{
    const float* x     = (const float*)d_in[0];
    const int*   nbrs  = (const int*)d_in[1];
    const float* param = (const float*)d_in[2];
    const int*   miter = (const int*)d_in[3];
    float*       out   = (float*)d_out;

    const int n = in_sizes[0] / 128;
    routing_kernel<<<n, 256>>>(x, nbrs, param, miter, out, n);
}